// round 6
// baseline (speedup 1.0000x reference)
#include <cuda_runtime.h>
#include <cuda_bf16.h>
#include <math.h>
#include <stdint.h>

#define NB 2
#define NL 5000
#define HW 256
#define NPIX 65536
#define CIN 256
#define CL 128
#define PL 64
#define EPSB 1e-5f

typedef unsigned long long ull;

// ---------------- device scratch (no allocations allowed) ----------------
__device__ float g_xbuf[(size_t)NB * NPIX * CL];   // fc1 output, [b][h][w][c]  (64 MB fp32)
__device__ uint32_t g_fc1ph[(CIN / 2) * CL];       // fc1_w bf16x2 hi, [kpair][o]
__device__ uint32_t g_fc1pl[(CIN / 2) * CL];       // fc1_w bf16x2 lo
__device__ float g_a1[CL], g_b1c[CL];              // BN1 fold
__device__ float2 g_w1p[(CL / 2) * PL];            // conv1 (BN2 folded), [cpair][o]
__device__ float g_b1f[PL];
__device__ float4 g_w2q[PL * PL];                  // conv2 (BN3 folded), [i][o] -> (w0,w1,w2,0)
__device__ float g_b2f[PL];
__device__ float2 g_w3p[(PL / 2) * CL];            // conv3, [ipair][o]

// ---------------- f32x2 helpers ----------------
__device__ __forceinline__ ull pk2(float lo, float hi) {
    ull r;
    asm("mov.b64 %0, {%1, %2};" : "=l"(r) : "f"(lo), "f"(hi));
    return r;
}
__device__ __forceinline__ void upk2(ull v, float& lo, float& hi) {
    asm("mov.b64 {%0, %1}, %2;" : "=f"(lo), "=f"(hi) : "l"(v));
}
__device__ __forceinline__ void fma2(ull& d, ull a, ull b) {
    asm("fma.rn.f32x2 %0, %1, %2, %0;" : "+l"(d) : "l"(a), "l"(b));
}

// bf16 2-term split of a pair (x -> lane0, y -> lane1)
__device__ __forceinline__ void sp2(float x, float y, uint32_t& h, uint32_t& l) {
    __nv_bfloat162 hb = __floats2bfloat162_rn(x, y);
    float lx = x - __low2float(hb);
    float ly = y - __high2float(hb);
    __nv_bfloat162 lb = __floats2bfloat162_rn(lx, ly);
    h = *reinterpret_cast<uint32_t*>(&hb);
    l = *reinterpret_cast<uint32_t*>(&lb);
}

// ---------------- prep: fold BN, transpose/split weights (grid-stride) ----------------
__global__ void prep_kernel(const float* __restrict__ fc1_w,
                            const float* __restrict__ bn1_g, const float* __restrict__ bn1_b,
                            const float* __restrict__ bn1_m, const float* __restrict__ bn1_v,
                            const float* __restrict__ conv1_w, const float* __restrict__ conv1_b,
                            const float* __restrict__ bn2_g, const float* __restrict__ bn2_b,
                            const float* __restrict__ bn2_m, const float* __restrict__ bn2_v,
                            const float* __restrict__ conv2_w, const float* __restrict__ conv2_b,
                            const float* __restrict__ bn3_g, const float* __restrict__ bn3_b,
                            const float* __restrict__ bn3_m, const float* __restrict__ bn3_v,
                            const float* __restrict__ conv3_w) {
    int tid = blockIdx.x * blockDim.x + threadIdx.x;
    int nt = gridDim.x * blockDim.x;
    for (int i = tid; i < CL; i += nt) {
        float a = bn1_g[i] * rsqrtf(bn1_v[i] + EPSB);
        g_a1[i]  = a;
        g_b1c[i] = bn1_b[i] - bn1_m[i] * a;
    }
    for (int i = tid; i < PL; i += nt) {
        float a2 = bn2_g[i] * rsqrtf(bn2_v[i] + EPSB);
        g_b1f[i] = conv1_b[i] * a2 + bn2_b[i] - bn2_m[i] * a2;
        float a3 = bn3_g[i] * rsqrtf(bn3_v[i] + EPSB);
        g_b2f[i] = conv2_b[i] * a3 + bn3_b[i] - bn3_m[i] * a3;
    }
    for (int i = tid; i < (CL / 2) * PL; i += nt) {
        int cp = i / PL, o = i % PL;
        float a2 = bn2_g[o] * rsqrtf(bn2_v[o] + EPSB);
        g_w1p[i] = make_float2(conv1_w[o * CL + 2 * cp] * a2,
                               conv1_w[o * CL + 2 * cp + 1] * a2);
    }
    for (int i = tid; i < PL * PL; i += nt) {
        int ii = i / PL, o = i % PL;
        float a3 = bn3_g[o] * rsqrtf(bn3_v[o] + EPSB);
        const float* wsrc = conv2_w + (o * PL + ii) * 3;
        g_w2q[i] = make_float4(wsrc[0] * a3, wsrc[1] * a3, wsrc[2] * a3, 0.0f);
    }
    for (int i = tid; i < (PL / 2) * CL; i += nt) {
        int ip = i / CL, o = i % CL;
        g_w3p[i] = make_float2(conv3_w[o * PL + 2 * ip], conv3_w[o * PL + 2 * ip + 1]);
    }
    // fc1 weights: transpose + bf16 hi/lo split packed over adjacent-k pairs
    for (int i = tid; i < (CIN / 2) * CL; i += nt) {
        int kp = i / CL, o = i % CL;
        uint32_t h, l;
        sp2(fc1_w[o * CIN + 2 * kp], fc1_w[o * CIN + 2 * kp + 1], h, l);
        g_fc1ph[i] = h;
        g_fc1pl[i] = l;
    }
}

// ---------------- fc1 via mma.sync bf16 m16n8k16, 2-term split / 3 products ----------------
__device__ __forceinline__ void mma_bf16(float* d, uint32_t a0, uint32_t a1,
                                         uint32_t a2, uint32_t a3,
                                         uint32_t b0, uint32_t b1) {
    asm volatile(
        "mma.sync.aligned.m16n8k16.row.col.f32.bf16.bf16.f32 "
        "{%0,%1,%2,%3}, {%4,%5,%6,%7}, {%8,%9}, {%0,%1,%2,%3};\n"
        : "+f"(d[0]), "+f"(d[1]), "+f"(d[2]), "+f"(d[3])
        : "r"(a0), "r"(a1), "r"(a2), "r"(a3), "r"(b0), "r"(b1));
}

__global__ __launch_bounds__(256) void fc1_tc_kernel(const float* __restrict__ feature,
                                                     const float* __restrict__ fc1_b) {
    __shared__ uint32_t Ah[16][136], Al[16][136];   // [kpair][px]
    __shared__ uint32_t Bh[16][136], Bl[16][136];   // [kpair][o]
    __shared__ float biass[128];

    int tid = threadIdx.x;
    long p0l = (long)blockIdx.x * 128;
    int b = (int)(p0l >> 16);
    int pix0 = (int)(p0l & 65535);
    const float* fb = feature + (size_t)b * CIN * NPIX + pix0;

    if (tid < 128) biass[tid] = fc1_b[tid];

    int wid = tid >> 5, lane = tid & 31;
    int warp_m = wid >> 2, warp_n = wid & 3;
    int grp = lane >> 2, qid = lane & 3;
    int pxb = warp_m * 64;
    int ob  = warp_n * 32;

    float acc[4][4][4];
#pragma unroll
    for (int mt = 0; mt < 4; mt++)
#pragma unroll
        for (int nt = 0; nt < 4; nt++)
#pragma unroll
            for (int j = 0; j < 4; j++) acc[mt][nt][j] = 0.0f;

    int p2  = tid >> 4;          // 0..15 k-pair within chunk
    int px0 = (tid & 15) * 8;    // 8 px (or o) per thread

    // prefetch chunk 0
    float4 A0a, A0b, A1a, A1b;
    uint4 Wh0, Wh1, Wl0, Wl1;
    {
        const float* fa = fb + (size_t)(2 * p2) * NPIX + px0;
        A0a = *(const float4*)fa;          A0b = *(const float4*)(fa + 4);
        A1a = *(const float4*)(fa + NPIX); A1b = *(const float4*)(fa + NPIX + 4);
        const uint32_t* wh = g_fc1ph + p2 * CL + px0;
        const uint32_t* wl = g_fc1pl + p2 * CL + px0;
        Wh0 = *(const uint4*)wh; Wh1 = *(const uint4*)(wh + 4);
        Wl0 = *(const uint4*)wl; Wl1 = *(const uint4*)(wl + 4);
    }

    for (int ch = 0; ch < 8; ch++) {
        __syncthreads();
        {
            uint4 th, tl;
            sp2(A0a.x, A1a.x, th.x, tl.x); sp2(A0a.y, A1a.y, th.y, tl.y);
            sp2(A0a.z, A1a.z, th.z, tl.z); sp2(A0a.w, A1a.w, th.w, tl.w);
            *(uint4*)&Ah[p2][px0] = th;     *(uint4*)&Al[p2][px0] = tl;
            sp2(A0b.x, A1b.x, th.x, tl.x); sp2(A0b.y, A1b.y, th.y, tl.y);
            sp2(A0b.z, A1b.z, th.z, tl.z); sp2(A0b.w, A1b.w, th.w, tl.w);
            *(uint4*)&Ah[p2][px0 + 4] = th; *(uint4*)&Al[p2][px0 + 4] = tl;
            *(uint4*)&Bh[p2][px0] = Wh0;    *(uint4*)&Bh[p2][px0 + 4] = Wh1;
            *(uint4*)&Bl[p2][px0] = Wl0;    *(uint4*)&Bl[p2][px0 + 4] = Wl1;
        }
        __syncthreads();
        if (ch < 7) {
            int c0 = (ch + 1) * 32;
            const float* fa = fb + (size_t)(c0 + 2 * p2) * NPIX + px0;
            A0a = *(const float4*)fa;          A0b = *(const float4*)(fa + 4);
            A1a = *(const float4*)(fa + NPIX); A1b = *(const float4*)(fa + NPIX + 4);
            const uint32_t* wh = g_fc1ph + ((ch + 1) * 16 + p2) * CL + px0;
            const uint32_t* wl = g_fc1pl + ((ch + 1) * 16 + p2) * CL + px0;
            Wh0 = *(const uint4*)wh; Wh1 = *(const uint4*)(wh + 4);
            Wl0 = *(const uint4*)wl; Wl1 = *(const uint4*)(wl + 4);
        }

#pragma unroll
        for (int ks = 0; ks < 2; ks++) {
            int r0 = ks * 8 + qid;
            const uint32_t* arh  = Ah[r0];
            const uint32_t* arh4 = Ah[r0 + 4];
            const uint32_t* arl  = Al[r0];
            const uint32_t* arl4 = Al[r0 + 4];
            uint32_t ah[4][4], al[4][4];
#pragma unroll
            for (int mt = 0; mt < 4; mt++) {
                int px = pxb + mt * 16 + grp;
                ah[mt][0] = arh[px];  ah[mt][1] = arh[px + 8];
                ah[mt][2] = arh4[px]; ah[mt][3] = arh4[px + 8];
                al[mt][0] = arl[px];  al[mt][1] = arl[px + 8];
                al[mt][2] = arl4[px]; al[mt][3] = arl4[px + 8];
            }
            const uint32_t* brh  = Bh[r0];
            const uint32_t* brh4 = Bh[r0 + 4];
            const uint32_t* brl  = Bl[r0];
            const uint32_t* brl4 = Bl[r0 + 4];
#pragma unroll
            for (int nt = 0; nt < 4; nt++) {
                int oo = ob + nt * 8 + grp;
                uint32_t bh0 = brh[oo], bh1 = brh4[oo];
                uint32_t bl0 = brl[oo], bl1 = brl4[oo];
#pragma unroll
                for (int mt = 0; mt < 4; mt++) {
                    mma_bf16(acc[mt][nt], ah[mt][0], ah[mt][1], ah[mt][2], ah[mt][3], bh0, bh1);
                    mma_bf16(acc[mt][nt], ah[mt][0], ah[mt][1], ah[mt][2], ah[mt][3], bl0, bl1);
                    mma_bf16(acc[mt][nt], al[mt][0], al[mt][1], al[mt][2], al[mt][3], bh0, bh1);
                }
            }
        }
    }

    // store fp32: c0=(r,2q) c1=(r,2q+1) c2=(r+8,2q) c3=(r+8,2q+1)
#pragma unroll
    for (int mt = 0; mt < 4; mt++) {
#pragma unroll
        for (int nt = 0; nt < 4; nt++) {
            int px = pix0 + pxb + mt * 16 + grp;
            int oo = ob + nt * 8 + qid * 2;
            float bx = biass[oo], by = biass[oo + 1];
            float2 r0 = make_float2(acc[mt][nt][0] + bx, acc[mt][nt][1] + by);
            float2 r1 = make_float2(acc[mt][nt][2] + bx, acc[mt][nt][3] + by);
            size_t base = ((size_t)b * NPIX + px) * CL + oo;
            *(float2*)&g_xbuf[base] = r0;
            *(float2*)&g_xbuf[base + (size_t)8 * CL] = r1;
        }
    }
}

// ---------------- per-line fused kernel ----------------
// 1 CTA (128 threads) per line. thread == channel for sampling / conv3 / fc2.
__global__ __launch_bounds__(128) void line_kernel(const float* __restrict__ lines,
                            const float* __restrict__ conv3_b,
                            const float* __restrict__ fc2_w,
                            const float* __restrict__ fc2_b,
                            float* __restrict__ out) {
    __shared__ int4   s_off[32];
    __shared__ float4 s_w[32];
    __shared__ float h0s[CL][8];
    __shared__ float h1s[PL][12];   // zero-padded: data at [o][1..8]
    __shared__ float h2s[PL][8];
    __shared__ float red[4][3];

    int tid = threadIdx.x;
    int n = blockIdx.x;
    int b = n / NL;

    if (tid < 32) {
        int p = tid;
        float lam = (float)p * (1.0f / 31.0f);
        const float* lp = lines + (size_t)n * 4;
        float px = lp[0] * lam + lp[2] * (1.0f - lam) - 0.5f;
        float py = lp[1] * lam + lp[3] * (1.0f - lam) - 0.5f;
        float px0 = fminf(fmaxf(floorf(px), 0.0f), 255.0f);
        float py0 = fminf(fmaxf(floorf(py), 0.0f), 255.0f);
        float px1 = fminf(px0 + 1.0f, 255.0f);
        float py1 = fminf(py0 + 1.0f, 255.0f);
        int ix0 = (int)px0, iy0 = (int)py0, ix1 = (int)px1, iy1 = (int)py1;
        s_off[p] = make_int4((ix0 * HW + iy0) * CL, (ix1 * HW + iy0) * CL,
                             (ix0 * HW + iy1) * CL, (ix1 * HW + iy1) * CL);
        s_w[p] = make_float4((px1 - px) * (py1 - py), (px - px0) * (py1 - py),
                             (px1 - px) * (py - py0), (px - px0) * (py - py0));
    }
    // zero conv2 padding rows
    for (int i = tid; i < PL * 12; i += 128) ((float*)h1s)[i] = 0.0f;
    __syncthreads();

    // ---- bilinear sample + maxpool(4) : thread = channel ----
    const float* xb = g_xbuf + (size_t)b * NPIX * CL + tid;
    float mx[8];
#pragma unroll
    for (int p = 0; p < 32; p++) {
        int4   off = s_off[p];
        float4 w   = s_w[p];
        float v = w.x * __ldg(xb + off.x)
                + w.y * __ldg(xb + off.y)
                + w.z * __ldg(xb + off.z)
                + w.w * __ldg(xb + off.w);
        int g = p >> 2;
        if ((p & 3) == 0) mx[g] = v; else mx[g] = fmaxf(mx[g], v);
    }

    // ---- BN1 + ReLU ----
    {
        float a1 = g_a1[tid], b1 = g_b1c[tid];
#pragma unroll
        for (int t = 0; t < 8; t++) h0s[tid][t] = fmaxf(mx[t] * a1 + b1, 0.0f);
    }
    __syncthreads();

    int o  = tid & 63;
    int th = tid >> 6;    // 0/1
    int t0 = th * 4;

    // ---- conv1 (1x1, 128->64) + BN2 + ReLU : f32x2 ----
    {
        ull a01 = 0ULL, a23 = 0ULL;
#pragma unroll 8
        for (int cp = 0; cp < CL / 2; cp++) {
            ulonglong2 ha = *(const ulonglong2*)&h0s[2 * cp][t0];       // (h[t0],h[t0+1]),(h[t0+2],h[t0+3])
            ulonglong2 hb = *(const ulonglong2*)&h0s[2 * cp + 1][t0];
            float2 w = __ldg(&g_w1p[cp * PL + o]);
            ull wx = pk2(w.x, w.x), wy = pk2(w.y, w.y);
            fma2(a01, ha.x, wx);
            fma2(a23, ha.y, wx);
            fma2(a01, hb.x, wy);
            fma2(a23, hb.y, wy);
        }
        float r0, r1, r2, r3;
        upk2(a01, r0, r1); upk2(a23, r2, r3);
        float bb = g_b1f[o];
        h1s[o][1 + t0 + 0] = fmaxf(r0 + bb, 0.0f);
        h1s[o][1 + t0 + 1] = fmaxf(r1 + bb, 0.0f);
        h1s[o][1 + t0 + 2] = fmaxf(r2 + bb, 0.0f);
        h1s[o][1 + t0 + 3] = fmaxf(r3 + bb, 0.0f);
    }
    __syncthreads();

    // ---- conv2 (k=3 pad=1, 64->64) + BN3 + ReLU : f32x2 ----
    {
        ull a01 = 0ULL, a23 = 0ULL;
#pragma unroll 8
        for (int i = 0; i < PL; i++) {
            float4 hv  = *(const float4*)&h1s[i][t0];
            float2 hv2 = *(const float2*)&h1s[i][t0 + 4];
            float4 w = __ldg(&g_w2q[i * PL + o]);
            ull wx = pk2(w.x, w.x), wy = pk2(w.y, w.y), wz = pk2(w.z, w.z);
            ull pxy = pk2(hv.x, hv.y);
            ull pyz = pk2(hv.y, hv.z);
            ull pzw = pk2(hv.z, hv.w);
            ull pw0 = pk2(hv.w, hv2.x);
            ull p01 = pk2(hv2.x, hv2.y);
            fma2(a01, pxy, wx);
            fma2(a01, pyz, wy);
            fma2(a01, pzw, wz);
            fma2(a23, pzw, wx);
            fma2(a23, pw0, wy);
            fma2(a23, p01, wz);
        }
        float r0, r1, r2, r3;
        upk2(a01, r0, r1); upk2(a23, r2, r3);
        float bb = g_b2f[o];
        h2s[o][t0 + 0] = fmaxf(r0 + bb, 0.0f);
        h2s[o][t0 + 1] = fmaxf(r1 + bb, 0.0f);
        h2s[o][t0 + 2] = fmaxf(r2 + bb, 0.0f);
        h2s[o][t0 + 3] = fmaxf(r3 + bb, 0.0f);
    }
    __syncthreads();

    // ---- conv3 (1x1, 64->128) + residual + ReLU : f32x2, thread = out channel ----
    float y[8];
    {
        ull acc[4] = {0ULL, 0ULL, 0ULL, 0ULL};
#pragma unroll 8
        for (int ip = 0; ip < PL / 2; ip++) {
            ulonglong2 h0lo = *(const ulonglong2*)&h2s[2 * ip][0];
            ulonglong2 h0hi = *(const ulonglong2*)&h2s[2 * ip][4];
            ulonglong2 h1lo = *(const ulonglong2*)&h2s[2 * ip + 1][0];
            ulonglong2 h1hi = *(const ulonglong2*)&h2s[2 * ip + 1][4];
            float2 w = __ldg(&g_w3p[ip * CL + tid]);
            ull wx = pk2(w.x, w.x), wy = pk2(w.y, w.y);
            fma2(acc[0], h0lo.x, wx);
            fma2(acc[1], h0lo.y, wx);
            fma2(acc[2], h0hi.x, wx);
            fma2(acc[3], h0hi.y, wx);
            fma2(acc[0], h1lo.x, wy);
            fma2(acc[1], h1lo.y, wy);
            fma2(acc[2], h1hi.x, wy);
            fma2(acc[3], h1hi.y, wy);
        }
        float cb = __ldg(&conv3_b[tid]);
        float a[8];
        upk2(acc[0], a[0], a[1]); upk2(acc[1], a[2], a[3]);
        upk2(acc[2], a[4], a[5]); upk2(acc[3], a[6], a[7]);
#pragma unroll
        for (int t = 0; t < 8; t++) y[t] = fmaxf(mx[t] + a[t] + cb, 0.0f);
    }

    // ---- fc2: [10000,1024] @ [1024,3]^T ----
    float s[3];
    const float4* fw = (const float4*)fc2_w;
#pragma unroll
    for (int k = 0; k < 3; k++) {
        float4 wa = __ldg(&fw[k * 256 + tid * 2]);
        float4 wb = __ldg(&fw[k * 256 + tid * 2 + 1]);
        s[k] = y[0] * wa.x + y[1] * wa.y + y[2] * wa.z + y[3] * wa.w
             + y[4] * wb.x + y[5] * wb.y + y[6] * wb.z + y[7] * wb.w;
    }
#pragma unroll
    for (int k = 0; k < 3; k++) {
#pragma unroll
        for (int off = 16; off > 0; off >>= 1)
            s[k] += __shfl_down_sync(0xffffffffu, s[k], off);
    }
    int wid = tid >> 5, lane = tid & 31;
    if (lane == 0) { red[wid][0] = s[0]; red[wid][1] = s[1]; red[wid][2] = s[2]; }
    __syncthreads();
    if (tid < 3) {
        out[(size_t)n * 3 + tid] = red[0][tid] + red[1][tid] + red[2][tid] + red[3][tid]
                                 + __ldg(&fc2_b[tid]);
    }
}

// ---------------- launch ----------------
extern "C" void kernel_launch(void* const* d_in, const int* in_sizes, int n_in,
                              void* d_out, int out_size) {
    const float* feature = (const float*)d_in[0];
    const float* lines   = (const float*)d_in[1];
    const float* fc1_w   = (const float*)d_in[2];
    const float* fc1_b   = (const float*)d_in[3];
    const float* bn1_g   = (const float*)d_in[4];
    const float* bn1_b   = (const float*)d_in[5];
    const float* bn1_m   = (const float*)d_in[6];
    const float* bn1_v   = (const float*)d_in[7];
    const float* conv1_w = (const float*)d_in[8];
    const float* conv1_b = (const float*)d_in[9];
    const float* bn2_g   = (const float*)d_in[10];
    const float* bn2_b   = (const float*)d_in[11];
    const float* bn2_m   = (const float*)d_in[12];
    const float* bn2_v   = (const float*)d_in[13];
    const float* conv2_w = (const float*)d_in[14];
    const float* conv2_b = (const float*)d_in[15];
    const float* bn3_g   = (const float*)d_in[16];
    const float* bn3_b   = (const float*)d_in[17];
    const float* bn3_m   = (const float*)d_in[18];
    const float* bn3_v   = (const float*)d_in[19];
    const float* conv3_w = (const float*)d_in[20];
    const float* conv3_b = (const float*)d_in[21];
    const float* fc2_w   = (const float*)d_in[22];
    const float* fc2_b   = (const float*)d_in[23];
    float* out = (float*)d_out;

    prep_kernel<<<64, 256>>>(fc1_w, bn1_g, bn1_b, bn1_m, bn1_v,
                             conv1_w, conv1_b, bn2_g, bn2_b, bn2_m, bn2_v,
                             conv2_w, conv2_b, bn3_g, bn3_b, bn3_m, bn3_v,
                             conv3_w);
    fc1_tc_kernel<<<(NB * NPIX) / 128, 256>>>(feature, fc1_b);
    line_kernel<<<NB * NL, 128>>>(lines, conv3_b, fc2_w, fc2_b, out);
}

// round 7
// speedup vs baseline: 1.5562x; 1.5562x over previous
#include <cuda_runtime.h>
#include <cuda_bf16.h>
#include <math.h>
#include <stdint.h>

#define NB 2
#define NL 5000
#define HW 256
#define NPIX 65536
#define CIN 256
#define CL 128
#define PL 64
#define EPSB 1e-5f

typedef unsigned long long ull;

// ---------------- device scratch (no allocations allowed) ----------------
__device__ float g_xbuf[(size_t)NB * NPIX * CL];   // fc1 output, [b][h][w][c]  (64 MB fp32)
__device__ uint32_t g_fc1ph[(CIN / 2) * CL];       // fc1_w bf16x2 hi, [kpair][o]
__device__ uint32_t g_fc1pl[(CIN / 2) * CL];       // fc1_w bf16x2 lo
__device__ float g_a1[CL], g_b1c[CL];              // BN1 fold
__device__ float2 g_w1p[(CL / 2) * PL];            // conv1 (BN2 folded), [cpair][o]
__device__ float g_b1f[PL];
__device__ float4 g_w2q[PL * PL];                  // conv2 (BN3 folded), [i][o] -> (w0,w1,w2,0)
__device__ float g_b2f[PL];
__device__ float2 g_w3p[(PL / 2) * CL];            // conv3, [ipair][o]

// ---------------- f32x2 helpers ----------------
__device__ __forceinline__ ull pk2(float lo, float hi) {
    ull r;
    asm("mov.b64 %0, {%1, %2};" : "=l"(r) : "f"(lo), "f"(hi));
    return r;
}
__device__ __forceinline__ void upk2(ull v, float& lo, float& hi) {
    asm("mov.b64 {%0, %1}, %2;" : "=f"(lo), "=f"(hi) : "l"(v));
}
__device__ __forceinline__ void fma2(ull& d, ull a, ull b) {
    asm("fma.rn.f32x2 %0, %1, %2, %0;" : "+l"(d) : "l"(a), "l"(b));
}

// bf16 2-term split of a pair (x -> lane0, y -> lane1)
__device__ __forceinline__ void sp2(float x, float y, uint32_t& h, uint32_t& l) {
    __nv_bfloat162 hb = __floats2bfloat162_rn(x, y);
    float lx = x - __low2float(hb);
    float ly = y - __high2float(hb);
    __nv_bfloat162 lb = __floats2bfloat162_rn(lx, ly);
    h = *reinterpret_cast<uint32_t*>(&hb);
    l = *reinterpret_cast<uint32_t*>(&lb);
}

// ---------------- prep: fold BN, transpose/split weights (grid-stride) ----------------
__global__ void prep_kernel(const float* __restrict__ fc1_w,
                            const float* __restrict__ bn1_g, const float* __restrict__ bn1_b,
                            const float* __restrict__ bn1_m, const float* __restrict__ bn1_v,
                            const float* __restrict__ conv1_w, const float* __restrict__ conv1_b,
                            const float* __restrict__ bn2_g, const float* __restrict__ bn2_b,
                            const float* __restrict__ bn2_m, const float* __restrict__ bn2_v,
                            const float* __restrict__ conv2_w, const float* __restrict__ conv2_b,
                            const float* __restrict__ bn3_g, const float* __restrict__ bn3_b,
                            const float* __restrict__ bn3_m, const float* __restrict__ bn3_v,
                            const float* __restrict__ conv3_w) {
    int tid = blockIdx.x * blockDim.x + threadIdx.x;
    int nt = gridDim.x * blockDim.x;
    for (int i = tid; i < CL; i += nt) {
        float a = bn1_g[i] * rsqrtf(bn1_v[i] + EPSB);
        g_a1[i]  = a;
        g_b1c[i] = bn1_b[i] - bn1_m[i] * a;
    }
    for (int i = tid; i < PL; i += nt) {
        float a2 = bn2_g[i] * rsqrtf(bn2_v[i] + EPSB);
        g_b1f[i] = conv1_b[i] * a2 + bn2_b[i] - bn2_m[i] * a2;
        float a3 = bn3_g[i] * rsqrtf(bn3_v[i] + EPSB);
        g_b2f[i] = conv2_b[i] * a3 + bn3_b[i] - bn3_m[i] * a3;
    }
    for (int i = tid; i < (CL / 2) * PL; i += nt) {
        int cp = i / PL, o = i % PL;
        float a2 = bn2_g[o] * rsqrtf(bn2_v[o] + EPSB);
        g_w1p[i] = make_float2(conv1_w[o * CL + 2 * cp] * a2,
                               conv1_w[o * CL + 2 * cp + 1] * a2);
    }
    for (int i = tid; i < PL * PL; i += nt) {
        int ii = i / PL, o = i % PL;
        float a3 = bn3_g[o] * rsqrtf(bn3_v[o] + EPSB);
        const float* wsrc = conv2_w + (o * PL + ii) * 3;
        g_w2q[i] = make_float4(wsrc[0] * a3, wsrc[1] * a3, wsrc[2] * a3, 0.0f);
    }
    for (int i = tid; i < (PL / 2) * CL; i += nt) {
        int ip = i / CL, o = i % CL;
        g_w3p[i] = make_float2(conv3_w[o * PL + 2 * ip], conv3_w[o * PL + 2 * ip + 1]);
    }
    // fc1 weights: transpose + bf16 hi/lo split packed over adjacent-k pairs
    for (int i = tid; i < (CIN / 2) * CL; i += nt) {
        int kp = i / CL, o = i % CL;
        uint32_t h, l;
        sp2(fc1_w[o * CIN + 2 * kp], fc1_w[o * CIN + 2 * kp + 1], h, l);
        g_fc1ph[i] = h;
        g_fc1pl[i] = l;
    }
}

// ---------------- fc1 via mma.sync bf16 m16n8k16, 2-term split / 3 products ----------------
__device__ __forceinline__ void mma_bf16(float* d, uint32_t a0, uint32_t a1,
                                         uint32_t a2, uint32_t a3,
                                         uint32_t b0, uint32_t b1) {
    asm volatile(
        "mma.sync.aligned.m16n8k16.row.col.f32.bf16.bf16.f32 "
        "{%0,%1,%2,%3}, {%4,%5,%6,%7}, {%8,%9}, {%0,%1,%2,%3};\n"
        : "+f"(d[0]), "+f"(d[1]), "+f"(d[2]), "+f"(d[3])
        : "r"(a0), "r"(a1), "r"(a2), "r"(a3), "r"(b0), "r"(b1));
}

__global__ __launch_bounds__(256) void fc1_tc_kernel(const float* __restrict__ feature,
                                                     const float* __restrict__ fc1_b) {
    __shared__ uint32_t Ah[16][136], Al[16][136];   // [kpair][px]
    __shared__ uint32_t Bh[16][136], Bl[16][136];   // [kpair][o]
    __shared__ float biass[128];

    int tid = threadIdx.x;
    long p0l = (long)blockIdx.x * 128;
    int b = (int)(p0l >> 16);
    int pix0 = (int)(p0l & 65535);
    const float* fb = feature + (size_t)b * CIN * NPIX + pix0;

    if (tid < 128) biass[tid] = fc1_b[tid];

    int wid = tid >> 5, lane = tid & 31;
    int warp_m = wid >> 2, warp_n = wid & 3;
    int grp = lane >> 2, qid = lane & 3;
    int pxb = warp_m * 64;
    int ob  = warp_n * 32;

    float acc[4][4][4];
#pragma unroll
    for (int mt = 0; mt < 4; mt++)
#pragma unroll
        for (int nt = 0; nt < 4; nt++)
#pragma unroll
            for (int j = 0; j < 4; j++) acc[mt][nt][j] = 0.0f;

    int p2  = tid >> 4;          // 0..15 k-pair within chunk
    int px0 = (tid & 15) * 8;    // 8 px (or o) per thread

    // prefetch chunk 0
    float4 A0a, A0b, A1a, A1b;
    uint4 Wh0, Wh1, Wl0, Wl1;
    {
        const float* fa = fb + (size_t)(2 * p2) * NPIX + px0;
        A0a = *(const float4*)fa;          A0b = *(const float4*)(fa + 4);
        A1a = *(const float4*)(fa + NPIX); A1b = *(const float4*)(fa + NPIX + 4);
        const uint32_t* wh = g_fc1ph + p2 * CL + px0;
        const uint32_t* wl = g_fc1pl + p2 * CL + px0;
        Wh0 = *(const uint4*)wh; Wh1 = *(const uint4*)(wh + 4);
        Wl0 = *(const uint4*)wl; Wl1 = *(const uint4*)(wl + 4);
    }

    for (int ch = 0; ch < 8; ch++) {
        __syncthreads();
        {
            uint4 th, tl;
            sp2(A0a.x, A1a.x, th.x, tl.x); sp2(A0a.y, A1a.y, th.y, tl.y);
            sp2(A0a.z, A1a.z, th.z, tl.z); sp2(A0a.w, A1a.w, th.w, tl.w);
            *(uint4*)&Ah[p2][px0] = th;     *(uint4*)&Al[p2][px0] = tl;
            sp2(A0b.x, A1b.x, th.x, tl.x); sp2(A0b.y, A1b.y, th.y, tl.y);
            sp2(A0b.z, A1b.z, th.z, tl.z); sp2(A0b.w, A1b.w, th.w, tl.w);
            *(uint4*)&Ah[p2][px0 + 4] = th; *(uint4*)&Al[p2][px0 + 4] = tl;
            *(uint4*)&Bh[p2][px0] = Wh0;    *(uint4*)&Bh[p2][px0 + 4] = Wh1;
            *(uint4*)&Bl[p2][px0] = Wl0;    *(uint4*)&Bl[p2][px0 + 4] = Wl1;
        }
        __syncthreads();
        if (ch < 7) {
            int c0 = (ch + 1) * 32;
            const float* fa = fb + (size_t)(c0 + 2 * p2) * NPIX + px0;
            A0a = *(const float4*)fa;          A0b = *(const float4*)(fa + 4);
            A1a = *(const float4*)(fa + NPIX); A1b = *(const float4*)(fa + NPIX + 4);
            const uint32_t* wh = g_fc1ph + ((ch + 1) * 16 + p2) * CL + px0;
            const uint32_t* wl = g_fc1pl + ((ch + 1) * 16 + p2) * CL + px0;
            Wh0 = *(const uint4*)wh; Wh1 = *(const uint4*)(wh + 4);
            Wl0 = *(const uint4*)wl; Wl1 = *(const uint4*)(wl + 4);
        }

#pragma unroll
        for (int ks = 0; ks < 2; ks++) {
            int r0 = ks * 8 + qid;
            const uint32_t* arh  = Ah[r0];
            const uint32_t* arh4 = Ah[r0 + 4];
            const uint32_t* arl  = Al[r0];
            const uint32_t* arl4 = Al[r0 + 4];
            uint32_t ah[4][4], al[4][4];
#pragma unroll
            for (int mt = 0; mt < 4; mt++) {
                int px = pxb + mt * 16 + grp;
                ah[mt][0] = arh[px];  ah[mt][1] = arh[px + 8];
                ah[mt][2] = arh4[px]; ah[mt][3] = arh4[px + 8];
                al[mt][0] = arl[px];  al[mt][1] = arl[px + 8];
                al[mt][2] = arl4[px]; al[mt][3] = arl4[px + 8];
            }
            const uint32_t* brh  = Bh[r0];
            const uint32_t* brh4 = Bh[r0 + 4];
            const uint32_t* brl  = Bl[r0];
            const uint32_t* brl4 = Bl[r0 + 4];
#pragma unroll
            for (int nt = 0; nt < 4; nt++) {
                int oo = ob + nt * 8 + grp;
                uint32_t bh0 = brh[oo], bh1 = brh4[oo];
                uint32_t bl0 = brl[oo], bl1 = brl4[oo];
#pragma unroll
                for (int mt = 0; mt < 4; mt++) {
                    mma_bf16(acc[mt][nt], ah[mt][0], ah[mt][1], ah[mt][2], ah[mt][3], bh0, bh1);
                    mma_bf16(acc[mt][nt], ah[mt][0], ah[mt][1], ah[mt][2], ah[mt][3], bl0, bl1);
                    mma_bf16(acc[mt][nt], al[mt][0], al[mt][1], al[mt][2], al[mt][3], bh0, bh1);
                }
            }
        }
    }

    // store fp32: c0=(r,2q) c1=(r,2q+1) c2=(r+8,2q) c3=(r+8,2q+1)
#pragma unroll
    for (int mt = 0; mt < 4; mt++) {
#pragma unroll
        for (int nt = 0; nt < 4; nt++) {
            int px = pix0 + pxb + mt * 16 + grp;
            int oo = ob + nt * 8 + qid * 2;
            float bx = biass[oo], by = biass[oo + 1];
            float2 r0 = make_float2(acc[mt][nt][0] + bx, acc[mt][nt][1] + by);
            float2 r1 = make_float2(acc[mt][nt][2] + bx, acc[mt][nt][3] + by);
            size_t base = ((size_t)b * NPIX + px) * CL + oo;
            *(float2*)&g_xbuf[base] = r0;
            *(float2*)&g_xbuf[base + (size_t)8 * CL] = r1;
        }
    }
}

// ---------------- per-line fused kernel ----------------
// 1 CTA (128 threads) per line. thread == channel for sampling / conv3 / fc2.
__global__ __launch_bounds__(128) void line_kernel(const float* __restrict__ lines,
                            const float* __restrict__ conv3_b,
                            const float* __restrict__ fc2_w,
                            const float* __restrict__ fc2_b,
                            float* __restrict__ out) {
    __shared__ int4   s_off[32];
    __shared__ float4 s_w[32];
    __shared__ float h0s[CL][8];
    __shared__ float h1s[PL][12];   // zero-padded: data at [o][1..8]
    __shared__ float h2s[PL][8];
    __shared__ float red[4][3];

    int tid = threadIdx.x;
    int n = blockIdx.x;
    int b = n / NL;

    if (tid < 32) {
        int p = tid;
        float lam = (float)p * (1.0f / 31.0f);
        const float* lp = lines + (size_t)n * 4;
        float px = lp[0] * lam + lp[2] * (1.0f - lam) - 0.5f;
        float py = lp[1] * lam + lp[3] * (1.0f - lam) - 0.5f;
        float px0 = fminf(fmaxf(floorf(px), 0.0f), 255.0f);
        float py0 = fminf(fmaxf(floorf(py), 0.0f), 255.0f);
        float px1 = fminf(px0 + 1.0f, 255.0f);
        float py1 = fminf(py0 + 1.0f, 255.0f);
        int ix0 = (int)px0, iy0 = (int)py0, ix1 = (int)px1, iy1 = (int)py1;
        s_off[p] = make_int4((ix0 * HW + iy0) * CL, (ix1 * HW + iy0) * CL,
                             (ix0 * HW + iy1) * CL, (ix1 * HW + iy1) * CL);
        s_w[p] = make_float4((px1 - px) * (py1 - py), (px - px0) * (py1 - py),
                             (px1 - px) * (py - py0), (px - px0) * (py - py0));
    }
    // zero conv2 padding rows
    for (int i = tid; i < PL * 12; i += 128) ((float*)h1s)[i] = 0.0f;
    __syncthreads();

    // ---- bilinear sample + maxpool(4) : thread = channel ----
    const float* xb = g_xbuf + (size_t)b * NPIX * CL + tid;
    float mx[8];
#pragma unroll
    for (int p = 0; p < 32; p++) {
        int4   off = s_off[p];
        float4 w   = s_w[p];
        float v = w.x * __ldg(xb + off.x)
                + w.y * __ldg(xb + off.y)
                + w.z * __ldg(xb + off.z)
                + w.w * __ldg(xb + off.w);
        int g = p >> 2;
        if ((p & 3) == 0) mx[g] = v; else mx[g] = fmaxf(mx[g], v);
    }

    // ---- BN1 + ReLU ----
    {
        float a1 = g_a1[tid], b1 = g_b1c[tid];
#pragma unroll
        for (int t = 0; t < 8; t++) h0s[tid][t] = fmaxf(mx[t] * a1 + b1, 0.0f);
    }
    __syncthreads();

    int o  = tid & 63;
    int th = tid >> 6;    // 0/1
    int t0 = th * 4;

    // ---- conv1 (1x1, 128->64) + BN2 + ReLU : f32x2 ----
    {
        ull a01 = 0ULL, a23 = 0ULL;
#pragma unroll 8
        for (int cp = 0; cp < CL / 2; cp++) {
            ulonglong2 ha = *(const ulonglong2*)&h0s[2 * cp][t0];       // (h[t0],h[t0+1]),(h[t0+2],h[t0+3])
            ulonglong2 hb = *(const ulonglong2*)&h0s[2 * cp + 1][t0];
            float2 w = __ldg(&g_w1p[cp * PL + o]);
            ull wx = pk2(w.x, w.x), wy = pk2(w.y, w.y);
            fma2(a01, ha.x, wx);
            fma2(a23, ha.y, wx);
            fma2(a01, hb.x, wy);
            fma2(a23, hb.y, wy);
        }
        float r0, r1, r2, r3;
        upk2(a01, r0, r1); upk2(a23, r2, r3);
        float bb = g_b1f[o];
        h1s[o][1 + t0 + 0] = fmaxf(r0 + bb, 0.0f);
        h1s[o][1 + t0 + 1] = fmaxf(r1 + bb, 0.0f);
        h1s[o][1 + t0 + 2] = fmaxf(r2 + bb, 0.0f);
        h1s[o][1 + t0 + 3] = fmaxf(r3 + bb, 0.0f);
    }
    __syncthreads();

    // ---- conv2 (k=3 pad=1, 64->64) + BN3 + ReLU : f32x2 ----
    {
        ull a01 = 0ULL, a23 = 0ULL;
#pragma unroll 8
        for (int i = 0; i < PL; i++) {
            float4 hv  = *(const float4*)&h1s[i][t0];
            float2 hv2 = *(const float2*)&h1s[i][t0 + 4];
            float4 w = __ldg(&g_w2q[i * PL + o]);
            ull wx = pk2(w.x, w.x), wy = pk2(w.y, w.y), wz = pk2(w.z, w.z);
            ull pxy = pk2(hv.x, hv.y);
            ull pyz = pk2(hv.y, hv.z);
            ull pzw = pk2(hv.z, hv.w);
            ull pw0 = pk2(hv.w, hv2.x);
            ull p01 = pk2(hv2.x, hv2.y);
            fma2(a01, pxy, wx);
            fma2(a01, pyz, wy);
            fma2(a01, pzw, wz);
            fma2(a23, pzw, wx);
            fma2(a23, pw0, wy);
            fma2(a23, p01, wz);
        }
        float r0, r1, r2, r3;
        upk2(a01, r0, r1); upk2(a23, r2, r3);
        float bb = g_b2f[o];
        h2s[o][t0 + 0] = fmaxf(r0 + bb, 0.0f);
        h2s[o][t0 + 1] = fmaxf(r1 + bb, 0.0f);
        h2s[o][t0 + 2] = fmaxf(r2 + bb, 0.0f);
        h2s[o][t0 + 3] = fmaxf(r3 + bb, 0.0f);
    }
    __syncthreads();

    // ---- conv3 (1x1, 64->128) + residual + ReLU : f32x2, thread = out channel ----
    float y[8];
    {
        ull acc[4] = {0ULL, 0ULL, 0ULL, 0ULL};
#pragma unroll 8
        for (int ip = 0; ip < PL / 2; ip++) {
            ulonglong2 h0lo = *(const ulonglong2*)&h2s[2 * ip][0];
            ulonglong2 h0hi = *(const ulonglong2*)&h2s[2 * ip][4];
            ulonglong2 h1lo = *(const ulonglong2*)&h2s[2 * ip + 1][0];
            ulonglong2 h1hi = *(const ulonglong2*)&h2s[2 * ip + 1][4];
            float2 w = __ldg(&g_w3p[ip * CL + tid]);
            ull wx = pk2(w.x, w.x), wy = pk2(w.y, w.y);
            fma2(acc[0], h0lo.x, wx);
            fma2(acc[1], h0lo.y, wx);
            fma2(acc[2], h0hi.x, wx);
            fma2(acc[3], h0hi.y, wx);
            fma2(acc[0], h1lo.x, wy);
            fma2(acc[1], h1lo.y, wy);
            fma2(acc[2], h1hi.x, wy);
            fma2(acc[3], h1hi.y, wy);
        }
        float cb = __ldg(&conv3_b[tid]);
        float a[8];
        upk2(acc[0], a[0], a[1]); upk2(acc[1], a[2], a[3]);
        upk2(acc[2], a[4], a[5]); upk2(acc[3], a[6], a[7]);
#pragma unroll
        for (int t = 0; t < 8; t++) y[t] = fmaxf(mx[t] + a[t] + cb, 0.0f);
    }

    // ---- fc2: [10000,1024] @ [1024,3]^T ----
    float s[3];
    const float4* fw = (const float4*)fc2_w;
#pragma unroll
    for (int k = 0; k < 3; k++) {
        float4 wa = __ldg(&fw[k * 256 + tid * 2]);
        float4 wb = __ldg(&fw[k * 256 + tid * 2 + 1]);
        s[k] = y[0] * wa.x + y[1] * wa.y + y[2] * wa.z + y[3] * wa.w
             + y[4] * wb.x + y[5] * wb.y + y[6] * wb.z + y[7] * wb.w;
    }
#pragma unroll
    for (int k = 0; k < 3; k++) {
#pragma unroll
        for (int off = 16; off > 0; off >>= 1)
            s[k] += __shfl_down_sync(0xffffffffu, s[k], off);
    }
    int wid = tid >> 5, lane = tid & 31;
    if (lane == 0) { red[wid][0] = s[0]; red[wid][1] = s[1]; red[wid][2] = s[2]; }
    __syncthreads();
    if (tid < 3) {
        out[(size_t)n * 3 + tid] = red[0][tid] + red[1][tid] + red[2][tid] + red[3][tid]
                                 + __ldg(&fc2_b[tid]);
    }
}

// ---------------- launch ----------------
extern "C" void kernel_launch(void* const* d_in, const int* in_sizes, int n_in,
                              void* d_out, int out_size) {
    const float* feature = (const float*)d_in[0];
    const float* lines   = (const float*)d_in[1];
    const float* fc1_w   = (const float*)d_in[2];
    const float* fc1_b   = (const float*)d_in[3];
    const float* bn1_g   = (const float*)d_in[4];
    const float* bn1_b   = (const float*)d_in[5];
    const float* bn1_m   = (const float*)d_in[6];
    const float* bn1_v   = (const float*)d_in[7];
    const float* conv1_w = (const float*)d_in[8];
    const float* conv1_b = (const float*)d_in[9];
    const float* bn2_g   = (const float*)d_in[10];
    const float* bn2_b   = (const float*)d_in[11];
    const float* bn2_m   = (const float*)d_in[12];
    const float* bn2_v   = (const float*)d_in[13];
    const float* conv2_w = (const float*)d_in[14];
    const float* conv2_b = (const float*)d_in[15];
    const float* bn3_g   = (const float*)d_in[16];
    const float* bn3_b   = (const float*)d_in[17];
    const float* bn3_m   = (const float*)d_in[18];
    const float* bn3_v   = (const float*)d_in[19];
    const float* conv3_w = (const float*)d_in[20];
    const float* conv3_b = (const float*)d_in[21];
    const float* fc2_w   = (const float*)d_in[22];
    const float* fc2_b   = (const float*)d_in[23];
    float* out = (float*)d_out;

    prep_kernel<<<64, 256>>>(fc1_w, bn1_g, bn1_b, bn1_m, bn1_v,
                             conv1_w, conv1_b, bn2_g, bn2_b, bn2_m, bn2_v,
                             conv2_w, conv2_b, bn3_g, bn3_b, bn3_m, bn3_v,
                             conv3_w);
    fc1_tc_kernel<<<(NB * NPIX) / 128, 256>>>(feature, fc1_b);
    line_kernel<<<NB * NL, 128>>>(lines, conv3_b, fc2_w, fc2_b, out);
}